// round 15
// baseline (speedup 1.0000x reference)
#include <cuda_runtime.h>
#include <cuda_fp16.h>

// DeepArcNet v8: fp16 m16n8k16 mma (same 11-bit mantissa as tf32, half the
// bytes, half the mma count). Weights precomputed as fp16 fragments in global
// (prep kernel). Activations dual-stored: fp32 [k][96] for scalar phases,
// fp16 [col][k] (stride 44 words, conflict-free B-frags) for gemm operands.
// Residual stream H kept full fp32.

#define TPB 192
#define SPB 16

typedef unsigned int uint32;

// fp32-word offsets in dynamic shared (112,400 B)
#define H32_F 0                      // [68][96] fp32 (residual, scalar reads)
#define A32_F 6528                   // [68][96] fp32 gemm C / conv scratch / fcw
#define B32_F 13056                  // [68][96] fp32 gemm C / fc reduce
#define HF_W  19584                  // fp16 [96 cols][88 k] as 96*44 u32
#define PF_W  23808                  // fp16 [96][88] (attn-out / ff1-out)
#define POS_F 28032                  // [68]
#define SM_FLOATS (POS_F + 68)       // 28100 words

#define CST 44                       // u32 words per fp16 column (88 fp16)

// 12 slots x 5 mtiles x 5 ktiles x 32 lanes, uint4 (8 fp16) each = 1.5MB
__device__ uint4 g_wfrag[12 * 5 * 5 * 32];

__device__ __forceinline__ uint32 pk16(float a, float b) {
  __half2 h = __floats2half2_rn(a, b);
  return *reinterpret_cast<uint32*>(&h);
}

__device__ __forceinline__ void mma16(float* c, const uint32* a, uint32 b0, uint32 b1) {
  asm volatile(
    "mma.sync.aligned.m16n8k16.row.col.f32.f16.f16.f32 "
    "{%0,%1,%2,%3},{%4,%5,%6,%7},{%8,%9},{%0,%1,%2,%3};"
    : "+f"(c[0]), "+f"(c[1]), "+f"(c[2]), "+f"(c[3])
    : "r"(a[0]), "r"(a[1]), "r"(a[2]), "r"(a[3]), "r"(b0), "r"(b1));
}

// ---- prep: fragment-major fp16 weights ----
__global__ void prep_kernel(const float* __restrict__ wq, const float* __restrict__ wk,
                            const float* __restrict__ wv, const float* __restrict__ projw,
                            const float* __restrict__ ff1w, const float* __restrict__ ff2w) {
  int idx = blockIdx.x * blockDim.x + threadIdx.x;
  if (idx >= 12 * 5 * 5 * 32) return;
  int lane = idx & 31;
  int kt = (idx >> 5) % 5;
  int mt = (idx / 160) % 5;
  int slot = idx / 800;
  int l = slot / 6, w = slot % 6;
  const float* src; int NR, K;
  switch (w) {
    case 0:  src = wq + l * 4624;    NR = 68; K = 68; break;
    case 1:  src = wk + l * 4624;    NR = 68; K = 68; break;
    case 2:  src = wv + l * 4624;    NR = 68; K = 68; break;
    case 3:  src = projw + l * 4624; NR = 68; K = 68; break;
    case 4:  src = ff1w + l * 2312;  NR = 34; K = 68; break;
    default: src = ff2w + l * 2312;  NR = 68; K = 34; break;
  }
  int gid = lane >> 2, tig = lane & 3;
  int r0 = mt * 16 + gid, r1 = r0 + 8;
  int k0 = kt * 16 + 2 * tig;
  auto rd = [&](int r, int k) -> float {
    return (r < NR && k < K) ? __ldg(src + r * K + k) : 0.f;
  };
  uint4 v;
  v.x = pk16(rd(r0, k0),     rd(r0, k0 + 1));
  v.y = pk16(rd(r1, k0),     rd(r1, k0 + 1));
  v.z = pk16(rd(r0, k0 + 8), rd(r0, k0 + 9));
  v.w = pk16(rd(r1, k0 + 8), rd(r1, k0 + 9));
  g_wfrag[idx] = v;
}

// ---- warp gemm: W(slot)[NR x K] * act -> dst (fp32 [NR][96]) or dsth (fp16 [col][88]) ----
__device__ __forceinline__ void gemm16(int slot, const uint32* bsrc,
                                       float* dst, __half* dsth,
                                       int NR, int KT, const float* __restrict__ bias,
                                       bool relu, int wid, int lane) {
  int gid = lane >> 2, tig = lane & 3;
  int mt, n0, nN;
  if (NR > 34) {
    if (wid < 4) { mt = wid; n0 = 0; nN = 12; }
    else         { mt = 4; n0 = (wid - 4) * 6; nN = 6; }
  } else {
    mt = wid >> 1; n0 = (wid & 1) * 6; nN = 6;
  }
  float acc[48];
#pragma unroll
  for (int i = 0; i < 48; i++) acc[i] = 0.f;

  const uint4* af = g_wfrag + (slot * 5 + mt) * 5 * 32 + lane;
#pragma unroll 1
  for (int kt = 0; kt < KT; kt++) {
    uint4 av = af[kt * 32];                    // one coalesced LDG.128 / warp
    uint32 a[4] = { av.x, av.y, av.z, av.w };
#pragma unroll
    for (int nt = 0; nt < 12; nt++) {
      if (nt < nN) {
        const uint32* bp = bsrc + ((n0 + nt) * 8 + gid) * CST + kt * 8 + tig;
        mma16(acc + nt * 4, a, bp[0], bp[4]);
      }
    }
  }

  int r0 = mt * 16 + gid, r1 = r0 + 8;
  float bz0 = (bias && r0 < NR) ? __ldg(bias + r0) : 0.f;
  float bz1 = (bias && r1 < NR) ? __ldg(bias + r1) : 0.f;
#pragma unroll
  for (int nt = 0; nt < 12; nt++) {
    if (nt < nN) {
      int col = (n0 + nt) * 8 + 2 * tig;
      float v0 = acc[nt * 4 + 0] + bz0, v1 = acc[nt * 4 + 1] + bz0;
      float v2 = acc[nt * 4 + 2] + bz1, v3 = acc[nt * 4 + 3] + bz1;
      if (relu) { v0 = fmaxf(v0, 0.f); v1 = fmaxf(v1, 0.f);
                  v2 = fmaxf(v2, 0.f); v3 = fmaxf(v3, 0.f); }
      if (dsth) {
        if (r0 < NR) { dsth[col * 88 + r0] = __float2half_rn(v0);
                       dsth[(col + 1) * 88 + r0] = __float2half_rn(v1); }
        if (r1 < NR) { dsth[col * 88 + r1] = __float2half_rn(v2);
                       dsth[(col + 1) * 88 + r1] = __float2half_rn(v3); }
      } else {
        if (r0 < NR) { dst[r0 * 96 + col] = v0; dst[r0 * 96 + col + 1] = v1; }
        if (r1 < NR) { dst[r1 * 96 + col] = v2; dst[r1 * 96 + col + 1] = v3; }
      }
    }
  }
}

__global__ void __launch_bounds__(TPB) dan_kernel(
    const float* __restrict__ x,     const float* __restrict__ convw,
    const float* __restrict__ convb, const float* __restrict__ lembw,
    const float* __restrict__ lembb, const float* __restrict__ projb,
    const float* __restrict__ ff1b,  const float* __restrict__ ff2b,
    const float* __restrict__ ln1g,  const float* __restrict__ ln1b,
    const float* __restrict__ ln2g,  const float* __restrict__ ln2b,
    const float* __restrict__ lnfg,  const float* __restrict__ lnfb,
    const float* __restrict__ fcw,   const float* __restrict__ fcb,
    float* __restrict__ out)
{
  extern __shared__ float smf[];
  float* Hs = smf + H32_F;
  float* As = smf + A32_F;
  float* Bs = smf + B32_F;
  uint32* hf = reinterpret_cast<uint32*>(smf + HF_W);
  uint32* pf = reinterpret_cast<uint32*>(smf + PF_W);
  __half* Ph = reinterpret_cast<__half*>(pf);
  const int tid = threadIdx.x;
  const int wid = tid >> 5, lane = tid & 31;
  const int samp0 = blockIdx.x * SPB;
  const int g = tid / 96, c = tid - g * 96;
  const int s = c / 6, t = c - s * 6;

  // pos table
  if (tid < 68) {
    int tt = tid >> 2, j4 = tid & 3;
    float ang = (j4 & 1) ? ((float)tt * (1.0f / 18.0f)) : (float)tt;
    smf[POS_F + tid] = (j4 < 2) ? sinf(ang) : cosf(ang);
  }
  // zero fp16 k-pads (words 34..39 = k 68..79)
#pragma unroll 1
  for (int idx = tid; idx < 96 * 6; idx += TPB) {
    int cc = idx / 6, w = 34 + idx % 6;
    hf[cc * CST + w] = 0u;
    pf[cc * CST + w] = 0u;
  }

  // depthwise conv 5x5 stride(2,2) -> scratch in A32
#pragma unroll 1
  for (int o = tid; o < SPB * 102; o += TPB) {
    int ss = o / 102, r = o % 102, ch = r / 17, tt = r % 17;
    const float* xp = x + ((size_t)(samp0 + ss) * 6 + ch) * 185 + tt * 10;
    float acc = 0.f;
#pragma unroll
    for (int i = 0; i < 25; i++) acc = fmaf(__ldg(xp + i), __ldg(convw + ch * 25 + i), acc);
    As[ss * 102 + ch * 17 + tt] = fmaxf(acc + __ldg(convb + ch), 0.f);
  }
  __syncthreads();

  // embed -> H32 (full fp32) + Hf (fp16 pairs)
  if (tid < 96) {
    float lw[4], lb[4];
#pragma unroll
    for (int q4 = 0; q4 < 4; q4++) {
      lw[q4] = __ldg(lembw + t * 4 + q4);
      lb[q4] = __ldg(lembb + t * 4 + q4);
    }
    float h0[68];
#pragma unroll 1
    for (int tt = 0; tt < 17; tt++) {
      float xv = As[s * 102 + t * 17 + tt];
#pragma unroll
      for (int q4 = 0; q4 < 4; q4++) {
        int e = tt * 4 + q4;
        h0[e] = fmaf(xv, lw[q4], lb[q4]) + smf[POS_F + e];
      }
    }
#pragma unroll
    for (int e = 0; e < 68; e++) Hs[e * 96 + c] = h0[e];
#pragma unroll
    for (int j = 0; j < 34; j++) hf[c * CST + j] = pk16(h0[2 * j], h0[2 * j + 1]);
  }
  __syncthreads();

  float p[6];  // softmax probs

#pragma unroll 1
  for (int l = 0; l < 2; l++) {
    int sl = l * 6;
    // Q -> A32, K -> B32
    gemm16(sl + 0, hf, As, nullptr, 68, 5, nullptr, false, wid, lane);
    gemm16(sl + 1, hf, Bs, nullptr, 68, 5, nullptr, false, wid, lane);
    __syncthreads();
    // softmax (A=Q, B=K -> p)
    {
      float qv[34];
#pragma unroll 1
      for (int d = 0; d < 34; d++) qv[d] = As[(g * 34 + d) * 96 + c];
      float sc[6];
#pragma unroll 1
      for (int t2 = 0; t2 < 6; t2++) {
        float a2 = 0.f;
#pragma unroll
        for (int d = 0; d < 34; d++)
          a2 = fmaf(qv[d], Bs[(g * 34 + d) * 96 + s * 6 + t2], a2);
        sc[t2] = a2 * 0.17149858514f;  // 34^-0.5
      }
      float mx = sc[0];
#pragma unroll
      for (int t2 = 1; t2 < 6; t2++) mx = fmaxf(mx, sc[t2]);
      float ssum = 0.f;
#pragma unroll
      for (int t2 = 0; t2 < 6; t2++) { sc[t2] = __expf(sc[t2] - mx); ssum += sc[t2]; }
      float inv = 1.0f / ssum;
#pragma unroll
      for (int t2 = 0; t2 < 6; t2++) p[t2] = sc[t2] * inv;
    }
    __syncthreads();
    // V -> A32 (Q consumed)
    gemm16(sl + 2, hf, As, nullptr, 68, 5, nullptr, false, wid, lane);
    __syncthreads();
    // attn = p*V -> Pf (fp16 pairs, k = g*34+dd)
    {
      float av[34];
#pragma unroll 1
      for (int dd = 0; dd < 34; dd++) {
        float a2 = 0.f;
#pragma unroll
        for (int t2 = 0; t2 < 6; t2++)
          a2 = fmaf(p[t2], As[(g * 34 + dd) * 96 + s * 6 + t2], a2);
        av[dd] = a2;
      }
#pragma unroll
      for (int j = 0; j < 17; j++)
        pf[c * CST + g * 17 + j] = pk16(av[2 * j], av[2 * j + 1]);
    }
    __syncthreads();
    // proj(Pf) -> A32 (+bias)
    gemm16(sl + 3, pf, As, nullptr, 68, 5, projb + l * 68, false, wid, lane);
    __syncthreads();
    // LN1: H = LN(H + A) -> H32 + Hf
    if (tid < 96) {
      float h[68]; float m = 0.f;
#pragma unroll
      for (int e = 0; e < 68; e++) { h[e] = Hs[e * 96 + c] + As[e * 96 + c]; m += h[e]; }
      m *= (1.0f / 68.0f);
      float v = 0.f;
#pragma unroll
      for (int e = 0; e < 68; e++) { float d = h[e] - m; v = fmaf(d, d, v); }
      float rr = rsqrtf(v * (1.0f / 68.0f) + 1e-5f);
#pragma unroll
      for (int e = 0; e < 68; e++) {
        h[e] = fmaf((h[e] - m) * rr, __ldg(ln1g + l * 68 + e), __ldg(ln1b + l * 68 + e));
        Hs[e * 96 + c] = h[e];
      }
#pragma unroll
      for (int j = 0; j < 34; j++) hf[c * CST + j] = pk16(h[2 * j], h[2 * j + 1]);
    }
    __syncthreads();
    // ff1(Hf) -> Pf fp16 (+bias, relu); zero k 34..47 band (words 17..23)
    gemm16(sl + 4, hf, nullptr, Ph, 34, 5, ff1b + l * 34, true, wid, lane);
#pragma unroll 1
    for (int idx = tid; idx < 96 * 7; idx += TPB) {
      int cc = idx / 7, w = 17 + idx % 7;
      pf[cc * CST + w] = 0u;
    }
    __syncthreads();
    // ff2(Pf, K=34->KT3) -> B32 (+bias)
    gemm16(sl + 5, pf, Bs, nullptr, 68, 3, ff2b + l * 68, false, wid, lane);
    __syncthreads();
    // LN2 (+final LN): H = LN(H + B) -> H32 (+Hf if l==0); stage fcw if l==1
    if (tid < 96) {
      float h[68]; float m = 0.f;
#pragma unroll
      for (int e = 0; e < 68; e++) { h[e] = Hs[e * 96 + c] + Bs[e * 96 + c]; m += h[e]; }
      m *= (1.0f / 68.0f);
      float v = 0.f;
#pragma unroll
      for (int e = 0; e < 68; e++) { float d = h[e] - m; v = fmaf(d, d, v); }
      float rr = rsqrtf(v * (1.0f / 68.0f) + 1e-5f);
#pragma unroll
      for (int e = 0; e < 68; e++)
        h[e] = fmaf((h[e] - m) * rr, __ldg(ln2g + l * 68 + e), __ldg(ln2b + l * 68 + e));
      if (l == 1) {
        m = 0.f;
#pragma unroll
        for (int e = 0; e < 68; e++) m += h[e];
        m *= (1.0f / 68.0f);
        v = 0.f;
#pragma unroll
        for (int e = 0; e < 68; e++) { float d = h[e] - m; v = fmaf(d, d, v); }
        rr = rsqrtf(v * (1.0f / 68.0f) + 1e-5f);
#pragma unroll
        for (int e = 0; e < 68; e++)
          h[e] = fmaf((h[e] - m) * rr, __ldg(lnfg + e), __ldg(lnfb + e));
      }
#pragma unroll
      for (int e = 0; e < 68; e++) Hs[e * 96 + c] = h[e];
      if (l == 0) {
#pragma unroll
        for (int j = 0; j < 34; j++) hf[c * CST + j] = pk16(h[2 * j], h[2 * j + 1]);
      }
    }
    if (l == 1) {
#pragma unroll 1
      for (int idx = tid; idx < 2448; idx += TPB) As[idx] = __ldg(fcw + idx);
    }
    __syncthreads();
  }

  // final FC [6 x 408] (weights in A32); partials -> B32; reduce
  if (tid < 96) {
    float h[68];
#pragma unroll
    for (int e = 0; e < 68; e++) h[e] = Hs[e * 96 + c];
#pragma unroll 1
    for (int o = 0; o < 6; o++) {
      const float* wrow = As + o * 408 + t * 68;
      float a2 = 0.f;
#pragma unroll
      for (int e = 0; e < 68; e++) a2 = fmaf(h[e], wrow[e], a2);
      Bs[s * 36 + t * 6 + o] = a2;
    }
  }
  __syncthreads();
  if (tid < SPB) {
    int ss = tid;
#pragma unroll 1
    for (int o = 0; o < 6; o++) {
      float v = __ldg(fcb + o);
#pragma unroll
      for (int tt = 0; tt < 6; tt++) v += Bs[ss * 36 + tt * 6 + o];
      out[(size_t)(samp0 + ss) * 6 + o] = fmaxf(v, 0.f);
    }
  }
}

extern "C" void kernel_launch(void* const* d_in, const int* in_sizes, int n_in,
                              void* d_out, int out_size) {
  const float* x     = (const float*)d_in[0];
  const float* convw = (const float*)d_in[1];
  const float* convb = (const float*)d_in[2];
  const float* lembw = (const float*)d_in[3];
  const float* lembb = (const float*)d_in[4];
  const float* wq    = (const float*)d_in[5];
  const float* wk    = (const float*)d_in[6];
  const float* wv    = (const float*)d_in[7];
  const float* projw = (const float*)d_in[8];
  const float* projb = (const float*)d_in[9];
  const float* ff1w  = (const float*)d_in[10];
  const float* ff1b  = (const float*)d_in[11];
  const float* ff2w  = (const float*)d_in[12];
  const float* ff2b  = (const float*)d_in[13];
  const float* ln1g  = (const float*)d_in[14];
  const float* ln1b  = (const float*)d_in[15];
  const float* ln2g  = (const float*)d_in[16];
  const float* ln2b  = (const float*)d_in[17];
  const float* lnfg  = (const float*)d_in[18];
  const float* lnfb  = (const float*)d_in[19];
  const float* fcw   = (const float*)d_in[20];
  const float* fcb   = (const float*)d_in[21];
  float* out = (float*)d_out;

  int B = in_sizes[0] / (6 * 37 * 5);   // 32768
  int grid = B / SPB;                   // 2048
  int smem = SM_FLOATS * 4;             // 112,400 B

  static int configured = 0;
  if (!configured) {
    cudaFuncSetAttribute(dan_kernel, cudaFuncAttributeMaxDynamicSharedMemorySize, smem);
    configured = 1;
  }
  prep_kernel<<<(12 * 5 * 5 * 32 + 255) / 256, 256>>>(wq, wk, wv, projw, ff1w, ff2w);
  dan_kernel<<<grid, TPB, smem>>>(
      x, convw, convb, lembw, lembb, projb, ff1b, ff2b,
      ln1g, ln1b, ln2g, ln2b, lnfg, lnfb, fcw, fcb, out);
}

// round 17
// speedup vs baseline: 1.4406x; 1.4406x over previous
#include <cuda_runtime.h>
#include <cuda_fp16.h>

// DeepArcNet v9: fp16 m16n8k16 mma, fragment-major precomputed weights (LDG),
// fp16 B operands stored [kpair][col] with stride 100 words -> conflict-free
// for BOTH gemm fragment reads and scalar pair writes (v8's [col][k] layout
// had 4-way write conflicts). ff1 output repacked via fp32 C + scalar phase.

#define TPB 192
#define SPB 16

typedef unsigned int uint32;

// fp32-word offsets in dynamic shared (110,608 B)
#define H32_F 0                      // [68][96] fp32 residual
#define A32_F 6528                   // [68][96] fp32 gemm C / conv scratch / fcw
#define B32_F 13056                  // [68][96] fp32 gemm C / fc reduce
#define HF_W  19584                  // fp16 H: u32 [40 kpairs][stride 100]
#define PF_W  23584                  // fp16 attn/ff1: u32 [40][100]
#define POS_F 27584                  // [68]
#define SM_FLOATS (POS_F + 68)       // 27652 words

#define KST 100                      // u32 words per kpair row

// 12 slots x 5 mtiles x 5 ktiles x 32 lanes, uint4 (8 fp16 each)
__device__ uint4 g_wfrag[12 * 5 * 5 * 32];

__device__ __forceinline__ uint32 pk16(float a, float b) {
  __half2 h = __floats2half2_rn(a, b);
  return *reinterpret_cast<uint32*>(&h);
}

__device__ __forceinline__ void mma16(float* c, const uint32* a, uint32 b0, uint32 b1) {
  asm volatile(
    "mma.sync.aligned.m16n8k16.row.col.f32.f16.f16.f32 "
    "{%0,%1,%2,%3},{%4,%5,%6,%7},{%8,%9},{%0,%1,%2,%3};"
    : "+f"(c[0]), "+f"(c[1]), "+f"(c[2]), "+f"(c[3])
    : "r"(a[0]), "r"(a[1]), "r"(a[2]), "r"(a[3]), "r"(b0), "r"(b1));
}

// ---- prep: fragment-major fp16 weights (validated in v8) ----
__global__ void prep_kernel(const float* __restrict__ wq, const float* __restrict__ wk,
                            const float* __restrict__ wv, const float* __restrict__ projw,
                            const float* __restrict__ ff1w, const float* __restrict__ ff2w) {
  int idx = blockIdx.x * blockDim.x + threadIdx.x;
  if (idx >= 12 * 5 * 5 * 32) return;
  int lane = idx & 31;
  int kt = (idx >> 5) % 5;
  int mt = (idx / 160) % 5;
  int slot = idx / 800;
  int l = slot / 6, w = slot % 6;
  const float* src; int NR, K;
  switch (w) {
    case 0:  src = wq + l * 4624;    NR = 68; K = 68; break;
    case 1:  src = wk + l * 4624;    NR = 68; K = 68; break;
    case 2:  src = wv + l * 4624;    NR = 68; K = 68; break;
    case 3:  src = projw + l * 4624; NR = 68; K = 68; break;
    case 4:  src = ff1w + l * 2312;  NR = 34; K = 68; break;
    default: src = ff2w + l * 2312;  NR = 68; K = 34; break;
  }
  int gid = lane >> 2, tig = lane & 3;
  int r0 = mt * 16 + gid, r1 = r0 + 8;
  int k0 = kt * 16 + 2 * tig;
  auto rd = [&](int r, int k) -> float {
    return (r < NR && k < K) ? __ldg(src + r * K + k) : 0.f;
  };
  uint4 v;
  v.x = pk16(rd(r0, k0),     rd(r0, k0 + 1));
  v.y = pk16(rd(r1, k0),     rd(r1, k0 + 1));
  v.z = pk16(rd(r0, k0 + 8), rd(r0, k0 + 9));
  v.w = pk16(rd(r1, k0 + 8), rd(r1, k0 + 9));
  g_wfrag[idx] = v;
}

// ---- warp gemm: W(slot)[NR x K] * B(fp16 [kpair][100]) -> dst fp32 [NR][96] ----
__device__ __forceinline__ void gemm16(int slot, const uint32* bsrc, float* dst,
                                       int NR, int KT, const float* __restrict__ bias,
                                       bool relu, int wid, int lane) {
  int gid = lane >> 2, tig = lane & 3;
  int mt, n0, nN;
  if (NR > 34) {
    if (wid < 4) { mt = wid; n0 = 0; nN = 12; }
    else         { mt = 4; n0 = (wid - 4) * 6; nN = 6; }
  } else {
    mt = wid >> 1; n0 = (wid & 1) * 6; nN = 6;
  }
  float acc[48];
#pragma unroll
  for (int i = 0; i < 48; i++) acc[i] = 0.f;

  const uint4* af = g_wfrag + (slot * 5 + mt) * 5 * 32 + lane;
#pragma unroll 1
  for (int kt = 0; kt < KT; kt++) {
    uint4 av = af[kt * 32];                    // one coalesced LDG.128 / warp
    uint32 a[4] = { av.x, av.y, av.z, av.w };
    const uint32* bp0 = bsrc + (kt * 8 + tig) * KST + gid;
#pragma unroll
    for (int nt = 0; nt < 12; nt++) {
      if (nt < nN) {
        const uint32* bp = bp0 + (n0 + nt) * 8;
        mma16(acc + nt * 4, a, bp[0], bp[4 * KST]);
      }
    }
  }

  int r0 = mt * 16 + gid, r1 = r0 + 8;
  float bz0 = (bias && r0 < NR) ? __ldg(bias + r0) : 0.f;
  float bz1 = (bias && r1 < NR) ? __ldg(bias + r1) : 0.f;
#pragma unroll
  for (int nt = 0; nt < 12; nt++) {
    if (nt < nN) {
      int col = (n0 + nt) * 8 + 2 * tig;
      float v0 = acc[nt * 4 + 0] + bz0, v1 = acc[nt * 4 + 1] + bz0;
      float v2 = acc[nt * 4 + 2] + bz1, v3 = acc[nt * 4 + 3] + bz1;
      if (relu) { v0 = fmaxf(v0, 0.f); v1 = fmaxf(v1, 0.f);
                  v2 = fmaxf(v2, 0.f); v3 = fmaxf(v3, 0.f); }
      if (r0 < NR) { dst[r0 * 96 + col] = v0; dst[r0 * 96 + col + 1] = v1; }
      if (r1 < NR) { dst[r1 * 96 + col] = v2; dst[r1 * 96 + col + 1] = v3; }
    }
  }
}

__global__ void __launch_bounds__(TPB) dan_kernel(
    const float* __restrict__ x,     const float* __restrict__ convw,
    const float* __restrict__ convb, const float* __restrict__ lembw,
    const float* __restrict__ lembb, const float* __restrict__ projb,
    const float* __restrict__ ff1b,  const float* __restrict__ ff2b,
    const float* __restrict__ ln1g,  const float* __restrict__ ln1b,
    const float* __restrict__ ln2g,  const float* __restrict__ ln2b,
    const float* __restrict__ lnfg,  const float* __restrict__ lnfb,
    const float* __restrict__ fcw,   const float* __restrict__ fcb,
    float* __restrict__ out)
{
  extern __shared__ float smf[];
  float* Hs = smf + H32_F;
  float* As = smf + A32_F;
  float* Bs = smf + B32_F;
  uint32* hf = reinterpret_cast<uint32*>(smf + HF_W);
  uint32* pf = reinterpret_cast<uint32*>(smf + PF_W);
  const int tid = threadIdx.x;
  const int wid = tid >> 5, lane = tid & 31;
  const int samp0 = blockIdx.x * SPB;
  const int g = tid / 96, c = tid - g * 96;
  const int s = c / 6, t = c - s * 6;

  // pos table
  if (tid < 68) {
    int tt = tid >> 2, j4 = tid & 3;
    float ang = (j4 & 1) ? ((float)tt * (1.0f / 18.0f)) : (float)tt;
    smf[POS_F + tid] = (j4 < 2) ? sinf(ang) : cosf(ang);
  }
  // zero k-pad rows (kpairs 34..39) of both fp16 buffers (A frags are zero
  // there, but B must be finite; uninitialized smem could encode NaN)
#pragma unroll 1
  for (int idx = tid; idx < 6 * 96; idx += TPB) {
    int j = 34 + idx / 96, cc = idx % 96;
    hf[j * KST + cc] = 0u;
    pf[j * KST + cc] = 0u;
  }

  // depthwise conv 5x5 stride(2,2) -> scratch in A32
#pragma unroll 1
  for (int o = tid; o < SPB * 102; o += TPB) {
    int ss = o / 102, r = o % 102, ch = r / 17, tt = r % 17;
    const float* xp = x + ((size_t)(samp0 + ss) * 6 + ch) * 185 + tt * 10;
    float acc = 0.f;
#pragma unroll
    for (int i = 0; i < 25; i++) acc = fmaf(__ldg(xp + i), __ldg(convw + ch * 25 + i), acc);
    As[ss * 102 + ch * 17 + tt] = fmaxf(acc + __ldg(convb + ch), 0.f);
  }
  __syncthreads();

  // embed -> H32 (fp32) + Hf (fp16 pairs, conflict-free)
  if (tid < 96) {
    float lw[4], lb[4];
#pragma unroll
    for (int q4 = 0; q4 < 4; q4++) {
      lw[q4] = __ldg(lembw + t * 4 + q4);
      lb[q4] = __ldg(lembb + t * 4 + q4);
    }
    float h0[68];
#pragma unroll 1
    for (int tt = 0; tt < 17; tt++) {
      float xv = As[s * 102 + t * 17 + tt];
#pragma unroll
      for (int q4 = 0; q4 < 4; q4++) {
        int e = tt * 4 + q4;
        h0[e] = fmaf(xv, lw[q4], lb[q4]) + smf[POS_F + e];
      }
    }
#pragma unroll
    for (int e = 0; e < 68; e++) Hs[e * 96 + c] = h0[e];
#pragma unroll
    for (int j = 0; j < 34; j++) hf[j * KST + c] = pk16(h0[2 * j], h0[2 * j + 1]);
  }
  __syncthreads();

  float p[6];  // softmax probs

#pragma unroll 1
  for (int l = 0; l < 2; l++) {
    int sl = l * 6;
    // Q -> A32, K -> B32
    gemm16(sl + 0, hf, As, 68, 5, nullptr, false, wid, lane);
    gemm16(sl + 1, hf, Bs, 68, 5, nullptr, false, wid, lane);
    __syncthreads();
    // softmax (A=Q, B=K -> p)
    {
      float qv[34];
#pragma unroll 1
      for (int d = 0; d < 34; d++) qv[d] = As[(g * 34 + d) * 96 + c];
      float sc[6];
#pragma unroll 1
      for (int t2 = 0; t2 < 6; t2++) {
        float a2 = 0.f;
#pragma unroll
        for (int d = 0; d < 34; d++)
          a2 = fmaf(qv[d], Bs[(g * 34 + d) * 96 + s * 6 + t2], a2);
        sc[t2] = a2 * 0.17149858514f;  // 34^-0.5
      }
      float mx = sc[0];
#pragma unroll
      for (int t2 = 1; t2 < 6; t2++) mx = fmaxf(mx, sc[t2]);
      float ssum = 0.f;
#pragma unroll
      for (int t2 = 0; t2 < 6; t2++) { sc[t2] = __expf(sc[t2] - mx); ssum += sc[t2]; }
      float inv = 1.0f / ssum;
#pragma unroll
      for (int t2 = 0; t2 < 6; t2++) p[t2] = sc[t2] * inv;
    }
    __syncthreads();
    // V -> A32 (Q consumed)
    gemm16(sl + 2, hf, As, 68, 5, nullptr, false, wid, lane);
    __syncthreads();
    // attn = p*V -> Pf (fp16 pairs; kpairs 0..33 across both heads)
    {
      float av[34];
#pragma unroll 1
      for (int dd = 0; dd < 34; dd++) {
        float a2 = 0.f;
#pragma unroll
        for (int t2 = 0; t2 < 6; t2++)
          a2 = fmaf(p[t2], As[(g * 34 + dd) * 96 + s * 6 + t2], a2);
        av[dd] = a2;
      }
#pragma unroll
      for (int j = 0; j < 17; j++)
        pf[(g * 17 + j) * KST + c] = pk16(av[2 * j], av[2 * j + 1]);
    }
    __syncthreads();
    // proj(Pf) -> A32 (+bias)
    gemm16(sl + 3, pf, As, 68, 5, projb + l * 68, false, wid, lane);
    __syncthreads();
    // LN1: H = LN(H + A) -> H32 + Hf
    if (tid < 96) {
      float h[68]; float m = 0.f;
#pragma unroll
      for (int e = 0; e < 68; e++) { h[e] = Hs[e * 96 + c] + As[e * 96 + c]; m += h[e]; }
      m *= (1.0f / 68.0f);
      float v = 0.f;
#pragma unroll
      for (int e = 0; e < 68; e++) { float d = h[e] - m; v = fmaf(d, d, v); }
      float rr = rsqrtf(v * (1.0f / 68.0f) + 1e-5f);
#pragma unroll
      for (int e = 0; e < 68; e++) {
        h[e] = fmaf((h[e] - m) * rr, __ldg(ln1g + l * 68 + e), __ldg(ln1b + l * 68 + e));
        Hs[e * 96 + c] = h[e];
      }
#pragma unroll
      for (int j = 0; j < 34; j++) hf[j * KST + c] = pk16(h[2 * j], h[2 * j + 1]);
    }
    __syncthreads();
    // ff1(Hf) -> A32 rows 0..33 (+bias, relu)
    gemm16(sl + 4, hf, As, 34, 5, ff1b + l * 34, true, wid, lane);
    __syncthreads();
    // repack ff1 output -> Pf kpairs 0..16 (kpairs 17..33 hold stale finite
    // attn data; ff2 A-frags are zero for k>=34... and for k in [34,48) the
    // A frags are zero so stale B there contributes nothing)
    if (tid < 96) {
#pragma unroll
      for (int j = 0; j < 17; j++)
        pf[j * KST + c] = pk16(As[(2 * j) * 96 + c], As[(2 * j + 1) * 96 + c]);
    }
    __syncthreads();
    // ff2(Pf, K=34 -> KT=3) -> B32 (+bias)
    gemm16(sl + 5, pf, Bs, 68, 3, ff2b + l * 68, false, wid, lane);
    __syncthreads();
    // LN2 (+final LN): H = LN(H + B) -> H32 (+Hf if l==0); stage fcw if l==1
    if (tid < 96) {
      float h[68]; float m = 0.f;
#pragma unroll
      for (int e = 0; e < 68; e++) { h[e] = Hs[e * 96 + c] + Bs[e * 96 + c]; m += h[e]; }
      m *= (1.0f / 68.0f);
      float v = 0.f;
#pragma unroll
      for (int e = 0; e < 68; e++) { float d = h[e] - m; v = fmaf(d, d, v); }
      float rr = rsqrtf(v * (1.0f / 68.0f) + 1e-5f);
#pragma unroll
      for (int e = 0; e < 68; e++)
        h[e] = fmaf((h[e] - m) * rr, __ldg(ln2g + l * 68 + e), __ldg(ln2b + l * 68 + e));
      if (l == 1) {
        m = 0.f;
#pragma unroll
        for (int e = 0; e < 68; e++) m += h[e];
        m *= (1.0f / 68.0f);
        v = 0.f;
#pragma unroll
        for (int e = 0; e < 68; e++) { float d = h[e] - m; v = fmaf(d, d, v); }
        rr = rsqrtf(v * (1.0f / 68.0f) + 1e-5f);
#pragma unroll
        for (int e = 0; e < 68; e++)
          h[e] = fmaf((h[e] - m) * rr, __ldg(lnfg + e), __ldg(lnfb + e));
      }
#pragma unroll
      for (int e = 0; e < 68; e++) Hs[e * 96 + c] = h[e];
      if (l == 0) {
#pragma unroll
        for (int j = 0; j < 34; j++) hf[j * KST + c] = pk16(h[2 * j], h[2 * j + 1]);
      }
    }
    if (l == 1) {
#pragma unroll 1
      for (int idx = tid; idx < 2448; idx += TPB) As[idx] = __ldg(fcw + idx);
    }
    __syncthreads();
  }

  // final FC [6 x 408] (weights in A32); partials -> B32; reduce
  if (tid < 96) {
    float h[68];
#pragma unroll
    for (int e = 0; e < 68; e++) h[e] = Hs[e * 96 + c];
#pragma unroll 1
    for (int o = 0; o < 6; o++) {
      const float* wrow = As + o * 408 + t * 68;
      float a2 = 0.f;
#pragma unroll
      for (int e = 0; e < 68; e++) a2 = fmaf(h[e], wrow[e], a2);
      Bs[s * 36 + t * 6 + o] = a2;
    }
  }
  __syncthreads();
  if (tid < SPB) {
    int ss = tid;
#pragma unroll 1
    for (int o = 0; o < 6; o++) {
      float v = __ldg(fcb + o);
#pragma unroll
      for (int tt = 0; tt < 6; tt++) v += Bs[ss * 36 + tt * 6 + o];
      out[(size_t)(samp0 + ss) * 6 + o] = fmaxf(v, 0.f);
    }
  }
}

extern "C" void kernel_launch(void* const* d_in, const int* in_sizes, int n_in,
                              void* d_out, int out_size) {
  const float* x     = (const float*)d_in[0];
  const float* convw = (const float*)d_in[1];
  const float* convb = (const float*)d_in[2];
  const float* lembw = (const float*)d_in[3];
  const float* lembb = (const float*)d_in[4];
  const float* wq    = (const float*)d_in[5];
  const float* wk    = (const float*)d_in[6];
  const float* wv    = (const float*)d_in[7];
  const float* projw = (const float*)d_in[8];
  const float* projb = (const float*)d_in[9];
  const float* ff1w  = (const float*)d_in[10];
  const float* ff1b  = (const float*)d_in[11];
  const float* ff2w  = (const float*)d_in[12];
  const float* ff2b  = (const float*)d_in[13];
  const float* ln1g  = (const float*)d_in[14];
  const float* ln1b  = (const float*)d_in[15];
  const float* ln2g  = (const float*)d_in[16];
  const float* ln2b  = (const float*)d_in[17];
  const float* lnfg  = (const float*)d_in[18];
  const float* lnfb  = (const float*)d_in[19];
  const float* fcw   = (const float*)d_in[20];
  const float* fcb   = (const float*)d_in[21];
  float* out = (float*)d_out;

  int B = in_sizes[0] / (6 * 37 * 5);   // 32768
  int grid = B / SPB;                   // 2048
  int smem = SM_FLOATS * 4;             // 110,608 B

  static int configured = 0;
  if (!configured) {
    cudaFuncSetAttribute(dan_kernel, cudaFuncAttributeMaxDynamicSharedMemorySize, smem);
    configured = 1;
  }
  prep_kernel<<<(12 * 5 * 5 * 32 + 255) / 256, 256>>>(wq, wk, wv, projw, ff1w, ff2w);
  dan_kernel<<<grid, TPB, smem>>>(
      x, convw, convb, lembw, lembb, projb, ff1b, ff2b,
      ln1g, ln1b, ln2g, ln2b, lnfg, lnfb, fcw, fcb, out);
}